// round 5
// baseline (speedup 1.0000x reference)
#include <cuda_runtime.h>
#include <cuda_fp16.h>

#define T 64
#define S_LEN 1024
#define BATCH 512
#define START_TAG 62
#define STOP_TAG 63

__device__ float g_diff[BATCH];

__global__ __launch_bounds__(128) void crf_warp_kernel(
    const float* __restrict__ feats,
    const float* __restrict__ trans,
    const void* __restrict__ tags_raw,
    const int* __restrict__ mask)
{
    const int wid = threadIdx.x >> 5;
    const int l   = threadIdx.x & 31;
    const int b   = blockIdx.x * 4 + wid;     // one batch per warp
    const int t0  = 2 * l;                    // lane owns adjacent tag pair
    const int t1  = 2 * l + 1;

    // per-warp double-buffered normalized-alpha vector (64 tags = 32 half2)
    __shared__ __align__(16) __half2 p_sh[4][2][32];

    // E rows (exp of transitions) for this lane's two tags, packed half2 over j.
    __half2 E0[32], E1[32];
    {
        const float* tr0 = trans + t0 * T;
        const float* tr1 = trans + t1 * T;
#pragma unroll
        for (int k = 0; k < 32; k++) {
            E0[k] = __floats2half2_rn(__expf(tr0[2 * k]), __expf(tr0[2 * k + 1]));
            E1[k] = __floats2half2_rn(__expf(tr1[2 * k]), __expf(tr1[2 * k + 1]));
        }
    }

    const float*  fb  = feats + (size_t)b * S_LEN * T;
    const float2* fb2 = (const float2*)fb;    // element s*32+l = feats[s][2l..2l+1]
    const int*    mb  = mask + (size_t)b * S_LEN;

    // init alpha: one-hot at START (exp(0)=1, exp(-10000)=0)
    float q0 = (t0 == START_TAG) ? 1.0f : 0.0f;
    float q1 = (t1 == START_TAG) ? 1.0f : 0.0f;
    float C  = 0.0f;                          // sum of pow2 exponents (log2 of scale)
    p_sh[wid][0][l] = __floats2half2_rn(q0, q1);
    __syncwarp();

    // 2-deep prefetch of feats pair + mask; exp(feat) computed off critical path
    float2 fA = fb2[l];        int mA = mb[0];
    float  eA0 = __expf(fA.x), eA1 = __expf(fA.y);
    float2 fB = fb2[32 + l];   int mB = mb[1];
    float  eB0 = __expf(fB.x), eB1 = __expf(fB.y);

    for (int s = 0; s < S_LEN; s++) {
        const float4* p4 = (const float4*)p_sh[wid][s & 1];

        // matvec: acc[r] = sum_j E[r][j] * q[j]   (half2, 4-way ILP per row)
        __half2 a0 = __float2half2_rn(0.f), a1 = a0, a2 = a0, a3 = a0;
        __half2 c0 = a0, c1 = a0, c2 = a0, c3 = a0;
#pragma unroll
        for (int kk = 0; kk < 8; kk++) {
            float4 v = p4[kk];
            __half2 v0 = *(__half2*)&v.x;
            __half2 v1 = *(__half2*)&v.y;
            __half2 v2 = *(__half2*)&v.z;
            __half2 v3 = *(__half2*)&v.w;
            a0 = __hfma2(E0[4 * kk + 0], v0, a0);
            a1 = __hfma2(E0[4 * kk + 1], v1, a1);
            a2 = __hfma2(E0[4 * kk + 2], v2, a2);
            a3 = __hfma2(E0[4 * kk + 3], v3, a3);
            c0 = __hfma2(E1[4 * kk + 0], v0, c0);
            c1 = __hfma2(E1[4 * kk + 1], v1, c1);
            c2 = __hfma2(E1[4 * kk + 2], v2, c2);
            c3 = __hfma2(E1[4 * kk + 3], v3, c3);
        }
        __half2 sa = __hadd2(__hadd2(a0, a1), __hadd2(a2, a3));
        __half2 sc = __hadd2(__hadd2(c0, c1), __hadd2(c2, c3));
        float u0 = fmaxf(__low2float(sa) + __high2float(sa), 1e-30f) * eA0;
        float u1 = fmaxf(__low2float(sc) + __high2float(sc), 1e-30f) * eA1;
        int mk = mA;

        // rotate prefetch pipeline (off critical path)
        fA = fB; mA = mB; eA0 = eB0; eA1 = eB1;
        int s2 = s + 2;
        if (s2 < S_LEN) {
            fB = fb2[s2 * 32 + l]; mB = mb[s2];
            eB0 = __expf(fB.x);    eB1 = __expf(fB.y);
        }

        if (mk) {                              // warp-uniform branch
            // norm = 2^(e-127) where e = exponent of max(u) (u > 0 so raw
            // float bits are monotone as unsigned)
            unsigned bm = __reduce_max_sync(0xffffffffu,
                                            __float_as_uint(fmaxf(u0, u1)));
            int e = (int)(bm >> 23) & 0xFF;
            float ninv = __uint_as_float((unsigned)(254 - e) << 23); // exact 2^(127-e)
            q0 = u0 * ninv;                    // q in (0, 2)
            q1 = u1 * ninv;
            C += (float)(e - 127);
        }
        p_sh[wid][(s + 1) & 1][l] = __floats2half2_rn(q0, q1);
        __syncwarp();
    }

    // Terminal: forward = C*ln2 + log( sum_i q_i * exp(trans[STOP,i]) )
    float w = q0 * __expf(trans[STOP_TAG * T + t0])
            + q1 * __expf(trans[STOP_TAG * T + t1]);
#pragma unroll
    for (int off = 16; off > 0; off >>= 1)
        w += __shfl_xor_sync(0xffffffffu, w, off);
    float fscore = C * 0.6931471805599453f + __logf(w);

    // -------- tags dtype autodetect (int64 vs int32) --------
    const int* tags32 = (const int*)tags_raw;
    int hi_or = 0;
    for (int i = l; i < 128; i += 32) hi_or |= tags32[2 * i + 1];
#pragma unroll
    for (int off = 16; off > 0; off >>= 1)
        hi_or |= __shfl_xor_sync(0xffffffffu, hi_or, off);
    const bool is64 = (hi_or == 0);
    const long long* tags64 = (const long long*)tags_raw;
    const size_t tbase = (size_t)b * S_LEN;

    // Gold path score (lane-strided gather over s)
    float gsum = 0.f;
    int   mcnt = 0;
    for (int s = l; s < S_LEN; s += 32) {
        int cur  = is64 ? (int)tags64[tbase + s] : tags32[tbase + s];
        int prev = (s == 0) ? START_TAG
                            : (is64 ? (int)tags64[tbase + s - 1] : tags32[tbase + s - 1]);
        int mk   = mb[s];
        if (mk) {
            gsum += fb[s * T + cur] + trans[cur * T + prev];
            mcnt++;
        }
    }
#pragma unroll
    for (int off = 16; off > 0; off >>= 1) {
        gsum += __shfl_xor_sync(0xffffffffu, gsum, off);
        mcnt += __shfl_xor_sync(0xffffffffu, mcnt, off);
    }
    if (l == 0) {
        int last_tag;
        if (mcnt == 0) last_tag = START_TAG;
        else last_tag = is64 ? (int)tags64[tbase + mcnt - 1] : tags32[tbase + mcnt - 1];
        float gold = gsum + trans[STOP_TAG * T + last_tag];
        g_diff[b] = fscore - gold;
    }
}

__global__ void crf_reduce_kernel(float* __restrict__ out)
{
    __shared__ float sm[BATCH];
    int t = threadIdx.x;
    sm[t] = g_diff[t];
    __syncthreads();
    for (int st = BATCH / 2; st > 0; st >>= 1) {
        if (t < st) sm[t] += sm[t + st];
        __syncthreads();
    }
    if (t == 0) out[0] = sm[0] * (1.0f / (float)BATCH);
}

extern "C" void kernel_launch(void* const* d_in, const int* in_sizes, int n_in,
                              void* d_out, int out_size)
{
    const float* feats = (const float*)d_in[0];
    const float* trans = (const float*)d_in[1];
    const void*  tags  = (const void*)d_in[2];
    const int*   mask  = (const int*)d_in[3];
    float* out = (float*)d_out;

    crf_warp_kernel<<<BATCH / 4, 128>>>(feats, trans, tags, mask);
    crf_reduce_kernel<<<1, BATCH>>>(out);
}

// round 6
// speedup vs baseline: 3.5650x; 3.5650x over previous
#include <cuda_runtime.h>
#include <cuda_bf16.h>

#define T 64
#define S_LEN 1024
#define BATCH 512
#define START_TAG 62
#define STOP_TAG 63
#define CHUNK 16
#define NCHUNK (S_LEN / CHUNK)

__device__ float g_diff[BATCH];

__device__ __forceinline__ void cp_async16(unsigned saddr, const void* g) {
    asm volatile("cp.async.cg.shared.global [%0], [%1], 16;\n" :: "r"(saddr), "l"(g));
}
__device__ __forceinline__ void cp_commit() {
    asm volatile("cp.async.commit_group;\n");
}
template <int N>
__device__ __forceinline__ void cp_wait() {
    asm volatile("cp.async.wait_group %0;\n" :: "n"(N));
}

__global__ __launch_bounds__(128) void crf_warp_kernel(
    const float* __restrict__ feats,
    const float* __restrict__ trans,
    const void* __restrict__ tags_raw,
    const int* __restrict__ mask)
{
    const int wid = threadIdx.x >> 5;
    const int l   = threadIdx.x & 31;
    const int b   = blockIdx.x * 4 + wid;     // one batch per warp
    const int t0  = 2 * l;
    const int t1  = 2 * l + 1;

    // feats staging: 4 warps x 2 bufs x 16 steps x 64 floats = 32 KB
    __shared__ __align__(16) float stage[4][2][CHUNK * T];
    // normalized alpha exchange (bf16x2), double-buffered
    __shared__ __align__(16) __nv_bfloat162 p_sh[4][2][32];

    // E rows for this lane's two tags, bf16x2 packed over j
    __nv_bfloat162 E0[32], E1[32];
    {
        const float* tr0 = trans + t0 * T;
        const float* tr1 = trans + t1 * T;
#pragma unroll
        for (int k = 0; k < 32; k++) {
            E0[k] = __floats2bfloat162_rn(__expf(tr0[2 * k]), __expf(tr0[2 * k + 1]));
            E1[k] = __floats2bfloat162_rn(__expf(tr1[2 * k]), __expf(tr1[2 * k + 1]));
        }
    }

    const float* fb = feats + (size_t)b * S_LEN * T;
    const int*   mb = mask + (size_t)b * S_LEN;

    // init alpha: one-hot at START
    float q0f = (t0 == START_TAG) ? 1.0f : 0.0f;
    float q1f = (t1 == START_TAG) ? 1.0f : 0.0f;
    int   C = 0;          // accumulated power-of-2 exponent (alpha = q * 2^C)
    int   r_prev = 127;   // stale exponent of max(u) for next normalization
    p_sh[wid][0][l] = __floats2bfloat162_rn(q0f, q1f);

    // mask register staging: lane l (<16) holds mask[c*16 + l]
    int mk_cur = (l < CHUNK) ? mb[l] : 0;
    int mk_nxt = (l < CHUNK) ? mb[CHUNK + l] : 0;

    // cp.async prologue: stage chunks 0 and 1
    const unsigned s0 = (unsigned)__cvta_generic_to_shared(&stage[wid][0][0]);
    const unsigned s1 = (unsigned)__cvta_generic_to_shared(&stage[wid][1][0]);
#pragma unroll
    for (int i = 0; i < 8; i++)
        cp_async16(s0 + (i * 32 + l) * 16, fb + (i * 32 + l) * 4);
    cp_commit();
#pragma unroll
    for (int i = 0; i < 8; i++)
        cp_async16(s1 + (i * 32 + l) * 16, fb + CHUNK * T + (i * 32 + l) * 4);
    cp_commit();
    __syncwarp();

    for (int c = 0; c < NCHUNK; c++) {
        const float* buf = stage[wid][c & 1];
        cp_wait<1>();
        __syncwarp();

        // peel: feats for local step 0
        float2 f = *(const float2*)(buf + 2 * l);
        float e0 = __expf(f.x), e1 = __expf(f.y);

#pragma unroll
        for (int ls = 0; ls < CHUNK; ls++) {
            const int par = ls & 1;           // (c*16+ls)&1 == ls&1
            int mk = __shfl_sync(0xffffffffu, mk_cur, ls);

            // prefetch next step's feats (within chunk) off the critical path
            float2 fn;
            if (ls + 1 < CHUNK)
                fn = *(const float2*)(buf + (ls + 1) * T + 2 * l);

            // matvec acc[r] = sum_j E[r][j] * q[j]  (bf16x2, 4-way ILP)
            const float4* p4 = (const float4*)p_sh[wid][par];
            __nv_bfloat162 A0 = __floats2bfloat162_rn(0.f, 0.f);
            __nv_bfloat162 A1 = A0, A2 = A0, A3 = A0;
            __nv_bfloat162 B0 = A0, B1 = A0, B2 = A0, B3 = A0;
#pragma unroll
            for (int kk = 0; kk < 8; kk++) {
                float4 v = p4[kk];
                __nv_bfloat162 v0 = *(__nv_bfloat162*)&v.x;
                __nv_bfloat162 v1 = *(__nv_bfloat162*)&v.y;
                __nv_bfloat162 v2 = *(__nv_bfloat162*)&v.z;
                __nv_bfloat162 v3 = *(__nv_bfloat162*)&v.w;
                A0 = __hfma2(E0[4 * kk + 0], v0, A0);
                A1 = __hfma2(E0[4 * kk + 1], v1, A1);
                A2 = __hfma2(E0[4 * kk + 2], v2, A2);
                A3 = __hfma2(E0[4 * kk + 3], v3, A3);
                B0 = __hfma2(E1[4 * kk + 0], v0, B0);
                B1 = __hfma2(E1[4 * kk + 1], v1, B1);
                B2 = __hfma2(E1[4 * kk + 2], v2, B2);
                B3 = __hfma2(E1[4 * kk + 3], v3, B3);
            }
            __nv_bfloat162 sA = __hadd2(__hadd2(A0, A1), __hadd2(A2, A3));
            __nv_bfloat162 sB = __hadd2(__hadd2(B0, B1), __hadd2(B2, B3));
            float u0 = (__low2float(sA) + __high2float(sA)) * e0;
            float u1 = (__low2float(sB) + __high2float(sB)) * e1;

            // exponent of warp max(u) -- consumed NEXT step (stale normalizer)
            unsigned rbits = __reduce_max_sync(0xffffffffu,
                                               __float_as_uint(fmaxf(u0, u1)));
            int e_this = (int)(rbits >> 23) & 0xFF;

            // normalize with stale exponent (exact power-of-2 scale)
            float ninv = __uint_as_float((unsigned)(254 - r_prev) << 23);
            float nq0 = u0 * ninv;
            float nq1 = u1 * ninv;
            q0f    = mk ? nq0 : q0f;
            q1f    = mk ? nq1 : q1f;
            C      = mk ? (C + r_prev - 127) : C;
            r_prev = mk ? e_this : r_prev;

            p_sh[wid][par ^ 1][l] = __floats2bfloat162_rn(q0f, q1f);
            __syncwarp();

            if (ls + 1 < CHUNK) { e0 = __expf(fn.x); e1 = __expf(fn.y); }
        }

        // rotate mask staging; refill this buffer with chunk c+2
        mk_cur = mk_nxt;
        if (c + 2 < NCHUNK) {
            mk_nxt = (l < CHUNK) ? mb[(c + 2) * CHUNK + l] : 0;
            __syncwarp();
            const unsigned sb = (c & 1) ? s1 : s0;
            const float* gsrc = fb + (c + 2) * CHUNK * T;
#pragma unroll
            for (int i = 0; i < 8; i++)
                cp_async16(sb + (i * 32 + l) * 16, gsrc + (i * 32 + l) * 4);
        }
        cp_commit();   // always commit (possibly empty group) to keep accounting
    }

    // forward = C*ln2 + log( sum_i q_i * exp(trans[STOP,i]) )
    float w = q0f * __expf(trans[STOP_TAG * T + t0])
            + q1f * __expf(trans[STOP_TAG * T + t1]);
#pragma unroll
    for (int off = 16; off > 0; off >>= 1)
        w += __shfl_xor_sync(0xffffffffu, w, off);
    float fscore = (float)C * 0.6931471805599453f + __logf(w);

    // -------- tags dtype autodetect (int64 vs int32) --------
    const int* tags32 = (const int*)tags_raw;
    int hi_or = 0;
    for (int i = l; i < 128; i += 32) hi_or |= tags32[2 * i + 1];
#pragma unroll
    for (int off = 16; off > 0; off >>= 1)
        hi_or |= __shfl_xor_sync(0xffffffffu, hi_or, off);
    const bool is64 = (hi_or == 0);
    const long long* tags64 = (const long long*)tags_raw;
    const size_t tbase = (size_t)b * S_LEN;

    // gold path score
    float gsum = 0.f;
    int   mcnt = 0;
    for (int s = l; s < S_LEN; s += 32) {
        int cur  = is64 ? (int)tags64[tbase + s] : tags32[tbase + s];
        int prev = (s == 0) ? START_TAG
                            : (is64 ? (int)tags64[tbase + s - 1] : tags32[tbase + s - 1]);
        int mk   = mb[s];
        if (mk) {
            gsum += fb[s * T + cur] + trans[cur * T + prev];
            mcnt++;
        }
    }
#pragma unroll
    for (int off = 16; off > 0; off >>= 1) {
        gsum += __shfl_xor_sync(0xffffffffu, gsum, off);
        mcnt += __shfl_xor_sync(0xffffffffu, mcnt, off);
    }
    if (l == 0) {
        int last_tag;
        if (mcnt == 0) last_tag = START_TAG;
        else last_tag = is64 ? (int)tags64[tbase + mcnt - 1] : tags32[tbase + mcnt - 1];
        float gold = gsum + trans[STOP_TAG * T + last_tag];
        g_diff[b] = fscore - gold;
    }
}

__global__ void crf_reduce_kernel(float* __restrict__ out)
{
    __shared__ float sm[BATCH];
    int t = threadIdx.x;
    sm[t] = g_diff[t];
    __syncthreads();
    for (int st = BATCH / 2; st > 0; st >>= 1) {
        if (t < st) sm[t] += sm[t + st];
        __syncthreads();
    }
    if (t == 0) out[0] = sm[0] * (1.0f / (float)BATCH);
}

// padding launches so ncu -s 5 -c 1 profiles crf_warp_kernel (launch idx 5)
__global__ void crf_dummy_kernel() {}

extern "C" void kernel_launch(void* const* d_in, const int* in_sizes, int n_in,
                              void* d_out, int out_size)
{
    const float* feats = (const float*)d_in[0];
    const float* trans = (const float*)d_in[1];
    const void*  tags  = (const void*)d_in[2];
    const int*   mask  = (const int*)d_in[3];
    float* out = (float*)d_out;

    crf_warp_kernel<<<BATCH / 4, 128>>>(feats, trans, tags, mask);
    crf_reduce_kernel<<<1, BATCH>>>(out);
    crf_dummy_kernel<<<1, 32>>>();
    crf_dummy_kernel<<<1, 32>>>();
    crf_dummy_kernel<<<1, 32>>>();
}